// round 13
// baseline (speedup 1.0000x reference)
#include <cuda_runtime.h>
#include <cuda_bf16.h>
#include <cstdint>
#include <math.h>

#define NN    100000
#define NPAD  100096
#define EE    1600000
#define FIN   27
#define EMB   64
#define HH    128
#define H3    384
#define LL    4
#define GG    512
#define SCAN_B 512
#define NBLK  ((NN + SCAN_B - 1) / SCAN_B)
#define GEMM_BY (NPAD / 128)      // 782
#define AGG_BY  3125              // 3125*4*8 = 100000 nodes
#define TOT_BY  (GEMM_BY + AGG_BY)

// ---------------- device scratch ----------------
__device__ float g_h0[NPAD * HH];
__device__ float g_h1[NPAD * HH];
__device__ __nv_bfloat16 g_hhi0[NPAD * HH];
__device__ __nv_bfloat16 g_hlo0[NPAD * HH];
__device__ __nv_bfloat16 g_hhi1[NPAD * HH];
__device__ __nv_bfloat16 g_hlo1[NPAD * HH];
__device__ __nv_bfloat16 g_aghi[NPAD * HH];
__device__ __nv_bfloat16 g_aglo[NPAD * HH];
__device__ float g_gh[NPAD * H3];
__device__ float g_cl[LL * HH * H3];
__device__ __nv_bfloat16 g_clT_hi[LL * H3 * HH];
__device__ __nv_bfloat16 g_clT_lo[LL * H3 * HH];
__device__ __nv_bfloat16 g_whh_hi[H3 * HH];
__device__ __nv_bfloat16 g_whh_lo[H3 * HH];
__device__ int   g_deg[NN];
__device__ int   g_rowptr[NN];
__device__ int   g_cursor[NN];
__device__ int   g_csr[EE];
__device__ int   g_bsums[NBLK];
__device__ float g_mu_all[GG];
__device__ float g_sig_all[GG];

__device__ __forceinline__ float sigmoidf_(float v) {
    return 1.0f / (1.0f + expf(-v));
}

__device__ __forceinline__ void mma16816(float* d, const uint32_t* a, const uint32_t* b) {
    asm volatile(
        "mma.sync.aligned.m16n8k16.row.col.f32.bf16.bf16.f32 {%0,%1,%2,%3}, {%4,%5,%6,%7}, {%8,%9}, {%0,%1,%2,%3};"
        : "+f"(d[0]), "+f"(d[1]), "+f"(d[2]), "+f"(d[3])
        : "r"(a[0]), "r"(a[1]), "r"(a[2]), "r"(a[3]), "r"(b[0]), "r"(b[1]));
}

// swizzled smem: row r (pitch 256B), 16B chunk ch stored at (ch ^ (r&7))
__device__ __forceinline__ uint32_t lds_frag(const char* base, int r, int kch, int t) {
    return *(const uint32_t*)(base + r * 256 + (((kch) ^ (r & 7)) << 4) + t * 4);
}

// ---------------- CSR build ----------------
__global__ void zero_deg_kernel() {
    int i = blockIdx.x * blockDim.x + threadIdx.x;
    if (i < NN) g_deg[i] = 0;
}
__global__ void zero_graph_kernel() {
    int i = threadIdx.x;
    if (i < GG) { g_mu_all[i] = 0.0f; g_sig_all[i] = 0.0f; }
}
__global__ void count_deg_kernel(const int* __restrict__ dst) {
    int e = blockIdx.x * blockDim.x + threadIdx.x;
    if (e < EE) atomicAdd(&g_deg[dst[e]], 1);
}
__global__ void scan1_kernel() {
    __shared__ int s[SCAN_B];
    int i = blockIdx.x * SCAN_B + threadIdx.x;
    int v = (i < NN) ? g_deg[i] : 0;
    s[threadIdx.x] = v;
    __syncthreads();
    for (int off = 1; off < SCAN_B; off <<= 1) {
        int t = 0;
        if (threadIdx.x >= off) t = s[threadIdx.x - off];
        __syncthreads();
        s[threadIdx.x] += t;
        __syncthreads();
    }
    if (i < NN) g_rowptr[i] = s[threadIdx.x] - v;
    if (threadIdx.x == SCAN_B - 1) g_bsums[blockIdx.x] = s[SCAN_B - 1];
}
__global__ void scan2_kernel() {
    if (threadIdx.x == 0) {
        int run = 0;
        for (int b = 0; b < NBLK; b++) { int t = g_bsums[b]; g_bsums[b] = run; run += t; }
    }
}
__global__ void scan3_kernel() {
    int i = blockIdx.x * blockDim.x + threadIdx.x;
    if (i < NN) {
        int v = g_rowptr[i] + g_bsums[i / SCAN_B];
        g_rowptr[i] = v;
        g_cursor[i] = v;
    }
}
__global__ void fill_csr_kernel(const int* __restrict__ src, const int* __restrict__ dst) {
    int e = blockIdx.x * blockDim.x + threadIdx.x;
    if (e < EE) {
        int p = atomicAdd(&g_cursor[dst[e]], 1);
        g_csr[p] = src[e];
    }
}

// ---------------- lin0 ----------------
__global__ void lin0_kernel(const float* __restrict__ x, const float* __restrict__ w,
                            float* __restrict__ out_x1) {
    int local = threadIdx.x >> 6;
    int j     = threadIdx.x & 63;
    int node  = blockIdx.x * 4 + local;
    __shared__ float xs[4][FIN];
    if (node < NN && j < FIN) xs[local][j] = x[node * FIN + j];
    __syncthreads();
    if (node >= NN) return;
    float acc = 0.0f;
#pragma unroll
    for (int k = 0; k < FIN; k++) acc += xs[local][k] * w[k * EMB + j];
    float v = sigmoidf_(acc);
    out_x1[node * EMB + j] = v;
    g_h0[node * HH + j] = v;
    g_h0[node * HH + EMB + j] = 0.0f;
    __nv_bfloat16 hi = __float2bfloat16(v);
    __nv_bfloat16 lo = __float2bfloat16(v - __bfloat162float(hi));
    g_hhi0[node * HH + j] = hi;
    g_hlo0[node * HH + j] = lo;
    g_hhi0[node * HH + EMB + j] = __float2bfloat16(0.0f);
    g_hlo0[node * HH + EMB + j] = __float2bfloat16(0.0f);
}

// ---------------- small fp32 GEMM (weight precompute only) ----------------
template <bool BT>
__global__ void gemm_kernel(const float* __restrict__ A, const float* __restrict__ B,
                            float* __restrict__ C, int M, int Ncol, int K) {
    const int BM = 64, BN = 64, BK = 16;
    __shared__ float As[BK][BM];
    __shared__ float Bs[BK][BN];
    int t  = threadIdx.x;
    int tx = t & 15, ty = t >> 4;
    int row0 = blockIdx.y * BM, col0 = blockIdx.x * BN;
    float acc[4][4] = {};
    for (int k0 = 0; k0 < K; k0 += BK) {
#pragma unroll
        for (int i = 0; i < 4; i++) {
            int idx = t + i * 256;
            int r = idx >> 4, c = idx & 15;
            int gr = row0 + r;
            As[c][r] = (gr < M) ? A[gr * K + k0 + c] : 0.0f;
        }
#pragma unroll
        for (int i = 0; i < 4; i++) {
            int idx = t + i * 256;
            if (BT) {
                int j = idx >> 4, c = idx & 15;
                Bs[c][j] = B[(col0 + j) * K + k0 + c];
            } else {
                int r = idx >> 6, j = idx & 63;
                Bs[r][j] = B[(k0 + r) * Ncol + col0 + j];
            }
        }
        __syncthreads();
#pragma unroll
        for (int k = 0; k < BK; k++) {
            float4 a4 = *(const float4*)&As[k][ty * 4];
            float4 b4 = *(const float4*)&Bs[k][tx * 4];
            float av[4]; float bv[4];
            av[0] = a4.x; av[1] = a4.y; av[2] = a4.z; av[3] = a4.w;
            bv[0] = b4.x; bv[1] = b4.y; bv[2] = b4.z; bv[3] = b4.w;
#pragma unroll
            for (int i = 0; i < 4; i++)
#pragma unroll
                for (int j = 0; j < 4; j++) acc[i][j] += av[i] * bv[j];
        }
        __syncthreads();
    }
#pragma unroll
    for (int i = 0; i < 4; i++) {
        int gr = row0 + ty * 4 + i;
        if (gr < M) {
#pragma unroll
            for (int j = 0; j < 4; j++) C[gr * Ncol + col0 + tx * 4 + j] = acc[i][j];
        }
    }
}

// ---------------- weight prep ----------------
__global__ void conv_cl_kernel() {
    int idx = blockIdx.x * blockDim.x + threadIdx.x;
    if (idx >= LL * H3 * HH) return;
    int l = idx / (H3 * HH);
    int rem = idx - l * H3 * HH;
    int n = rem >> 7, k = rem & 127;
    float v = g_cl[l * HH * H3 + k * H3 + n];
    __nv_bfloat16 hi = __float2bfloat16(v);
    g_clT_hi[idx] = hi;
    g_clT_lo[idx] = __float2bfloat16(v - __bfloat162float(hi));
}
__global__ void conv_whh_kernel(const float* __restrict__ w) {
    int idx = blockIdx.x * blockDim.x + threadIdx.x;
    if (idx >= H3 * HH) return;
    float v = w[idx];
    __nv_bfloat16 hi = __float2bfloat16(v);
    g_whh_hi[idx] = hi;
    g_whh_lo[idx] = __float2bfloat16(v - __bfloat162float(hi));
}

// ---------------- GEMM core (R8 structure): 128 rows x 96 gate-cols, 2 CTAs/SM ----------------
#define SM_A_HI 0
#define SM_A_LO 32768
#define SM_B_HI 65536
#define SM_B_LO 90112
#define GSMEM   114688

// Shared device function: load tiles + run 8-kstep dual-pass MMA, acc[2][6][4].
__device__ __forceinline__ void gemm_tile_body(
    const __nv_bfloat16* __restrict__ Ahi, const __nv_bfloat16* __restrict__ Alo,
    const __nv_bfloat16* __restrict__ Bhi, const __nv_bfloat16* __restrict__ Blo,
    char* smem, int row0, int j0, float acc[2][6][4]) {
    int tid = threadIdx.x;
    int wid = tid >> 5, lane = tid & 31;
    int g = lane >> 2, t = lane & 3;
    int rowg = wid & 3, colg = wid >> 2;

    for (int i = tid; i < 2048; i += 256) {
        int r = i >> 4, ch = i & 15;
        int dstoff = r * 256 + ((ch ^ (r & 7)) << 4);
        *(uint4*)(smem + SM_A_HI + dstoff) = *(const uint4*)&Ahi[(size_t)(row0 + r) * 128 + ch * 8];
        *(uint4*)(smem + SM_A_LO + dstoff) = *(const uint4*)&Alo[(size_t)(row0 + r) * 128 + ch * 8];
    }
    for (int i = tid; i < 1536; i += 256) {
        int br = i >> 4, ch = i & 15;
        int n = (br >> 5) * 128 + j0 + (br & 31);
        int dstoff = br * 256 + ((ch ^ (br & 7)) << 4);
        *(uint4*)(smem + SM_B_HI + dstoff) = *(const uint4*)&Bhi[(size_t)n * 128 + ch * 8];
        *(uint4*)(smem + SM_B_LO + dstoff) = *(const uint4*)&Blo[(size_t)n * 128 + ch * 8];
    }
    __syncthreads();

#pragma unroll
    for (int ks = 0; ks < 8; ks++) {
        uint32_t ah[2][4], al[2][4];
#pragma unroll
        for (int mt = 0; mt < 2; mt++) {
            int r1 = rowg * 32 + mt * 16 + g;
            int r2 = r1 + 8;
            ah[mt][0] = lds_frag(smem + SM_A_HI, r1, 2 * ks, t);
            ah[mt][1] = lds_frag(smem + SM_A_HI, r2, 2 * ks, t);
            ah[mt][2] = lds_frag(smem + SM_A_HI, r1, 2 * ks + 1, t);
            ah[mt][3] = lds_frag(smem + SM_A_HI, r2, 2 * ks + 1, t);
            al[mt][0] = lds_frag(smem + SM_A_LO, r1, 2 * ks, t);
            al[mt][1] = lds_frag(smem + SM_A_LO, r2, 2 * ks, t);
            al[mt][2] = lds_frag(smem + SM_A_LO, r1, 2 * ks + 1, t);
            al[mt][3] = lds_frag(smem + SM_A_LO, r2, 2 * ks + 1, t);
        }
#pragma unroll
        for (int nt = 0; nt < 6; nt++) {
            int br = (nt >> 1) * 32 + colg * 16 + (nt & 1) * 8 + g;
            uint32_t bh[2], bl[2];
            bh[0] = lds_frag(smem + SM_B_HI, br, 2 * ks, t);
            bh[1] = lds_frag(smem + SM_B_HI, br, 2 * ks + 1, t);
            bl[0] = lds_frag(smem + SM_B_LO, br, 2 * ks, t);
            bl[1] = lds_frag(smem + SM_B_LO, br, 2 * ks + 1, t);
#pragma unroll
            for (int mt = 0; mt < 2; mt++) {
                mma16816(acc[mt][nt], ah[mt], bh);
                mma16816(acc[mt][nt], ah[mt], bl);
                mma16816(acc[mt][nt], al[mt], bh);
            }
        }
    }
}

// ---------------- combined kernel: gh-GEMM CTAs + agg CTAs in one launch ----------------
// by < GEMM_BY: gh = h@Whh^T for (128 rows, 96 gate-cols) tile -> g_gh.
// by >= GEMM_BY: CSR gather, warp per node (8 nodes per CTA).
__global__ void __launch_bounds__(256, 2)
combined_gh_agg_kernel(const __nv_bfloat16* __restrict__ Hhi, const __nv_bfloat16* __restrict__ Hlo,
                       const __nv_bfloat16* __restrict__ Bwhi, const __nv_bfloat16* __restrict__ Bwlo,
                       const float* __restrict__ hcur,
                       __nv_bfloat16* __restrict__ aghi, __nv_bfloat16* __restrict__ aglo) {
    if (blockIdx.y >= GEMM_BY) {
        // ---- agg path ----
        int aggBlock = blockIdx.y - GEMM_BY;                  // 0..3124
        int wid = threadIdx.x >> 5, lane = threadIdx.x & 31;
        int n = (aggBlock * 4 + blockIdx.x) * 8 + wid;
        if (n >= NN) return;
        int s0 = g_rowptr[n];
        int d  = g_deg[n];
        float4 acc; acc.x = 0.0f; acc.y = 0.0f; acc.z = 0.0f; acc.w = 0.0f;
        int e = 0;
        for (; e + 4 <= d; e += 4) {
            int s1 = g_csr[s0 + e];
            int s2 = g_csr[s0 + e + 1];
            int s3 = g_csr[s0 + e + 2];
            int s4 = g_csr[s0 + e + 3];
            float4 v1 = *(const float4*)&hcur[(size_t)s1 * HH + lane * 4];
            float4 v2 = *(const float4*)&hcur[(size_t)s2 * HH + lane * 4];
            float4 v3 = *(const float4*)&hcur[(size_t)s3 * HH + lane * 4];
            float4 v4 = *(const float4*)&hcur[(size_t)s4 * HH + lane * 4];
            acc.x += (v1.x + v2.x) + (v3.x + v4.x);
            acc.y += (v1.y + v2.y) + (v3.y + v4.y);
            acc.z += (v1.z + v2.z) + (v3.z + v4.z);
            acc.w += (v1.w + v2.w) + (v3.w + v4.w);
        }
        for (; e < d; e++) {
            int s1 = g_csr[s0 + e];
            float4 v1 = *(const float4*)&hcur[(size_t)s1 * HH + lane * 4];
            acc.x += v1.x; acc.y += v1.y; acc.z += v1.z; acc.w += v1.w;
        }
        float vals[4]; vals[0] = acc.x; vals[1] = acc.y; vals[2] = acc.z; vals[3] = acc.w;
        __nv_bfloat162 hi01, hi23, lo01, lo23;
        __nv_bfloat16 h0 = __float2bfloat16(vals[0]);
        __nv_bfloat16 h1 = __float2bfloat16(vals[1]);
        __nv_bfloat16 h2 = __float2bfloat16(vals[2]);
        __nv_bfloat16 h3 = __float2bfloat16(vals[3]);
        hi01.x = h0; hi01.y = h1; hi23.x = h2; hi23.y = h3;
        lo01.x = __float2bfloat16(vals[0] - __bfloat162float(h0));
        lo01.y = __float2bfloat16(vals[1] - __bfloat162float(h1));
        lo23.x = __float2bfloat16(vals[2] - __bfloat162float(h2));
        lo23.y = __float2bfloat16(vals[3] - __bfloat162float(h3));
        *(__nv_bfloat162*)&aghi[(size_t)n * HH + lane * 4]     = hi01;
        *(__nv_bfloat162*)&aghi[(size_t)n * HH + lane * 4 + 2] = hi23;
        *(__nv_bfloat162*)&aglo[(size_t)n * HH + lane * 4]     = lo01;
        *(__nv_bfloat162*)&aglo[(size_t)n * HH + lane * 4 + 2] = lo23;
        return;
    }
    // ---- gh GEMM path ----
    extern __shared__ __align__(16) char smem[];
    int row0 = blockIdx.y * 128;
    int j0 = blockIdx.x * 32;
    float acc[2][6][4];
#pragma unroll
    for (int mt = 0; mt < 2; mt++)
#pragma unroll
        for (int nt = 0; nt < 6; nt++)
#pragma unroll
            for (int q = 0; q < 4; q++) acc[mt][nt][q] = 0.0f;

    gemm_tile_body(Hhi, Hlo, Bwhi, Bwlo, smem, row0, j0, acc);

    int wid = threadIdx.x >> 5, lane = threadIdx.x & 31;
    int g = lane >> 2, t = lane & 3;
    int rowg = wid & 3, colg = wid >> 2;
#pragma unroll
    for (int mt = 0; mt < 2; mt++) {
        int rbase = row0 + rowg * 32 + mt * 16 + g;
#pragma unroll
        for (int sub = 0; sub < 2; sub++) {
            int jj = j0 + colg * 16 + sub * 8 + t * 2;
#pragma unroll
            for (int g3 = 0; g3 < 3; g3++) {
                int nt = 2 * g3 + sub;
                float2 v0; v0.x = acc[mt][nt][0]; v0.y = acc[mt][nt][1];
                float2 v1; v1.x = acc[mt][nt][2]; v1.y = acc[mt][nt][3];
                *(float2*)&g_gh[(size_t)rbase * H3 + g3 * 128 + jj] = v0;
                *(float2*)&g_gh[(size_t)(rbase + 8) * H3 + g3 * 128 + jj] = v1;
            }
        }
    }
}

// ---------------- gi-GEMM + GRU gates kernel (reads gh buffer) ----------------
__global__ void __launch_bounds__(256, 2)
gates_kernel(const __nv_bfloat16* __restrict__ Aghi, const __nv_bfloat16* __restrict__ Aglo,
             const __nv_bfloat16* __restrict__ Bchi, const __nv_bfloat16* __restrict__ Bclo,
             const float* __restrict__ b_ih, const float* __restrict__ b_hh,
             const float* __restrict__ hprev,
             float* __restrict__ hout,
             __nv_bfloat16* __restrict__ houthi, __nv_bfloat16* __restrict__ houtlo) {
    extern __shared__ __align__(16) char smem[];
    int row0 = blockIdx.y * 128;
    int j0 = blockIdx.x * 32;
    float acc[2][6][4];
#pragma unroll
    for (int mt = 0; mt < 2; mt++)
#pragma unroll
        for (int nt = 0; nt < 6; nt++)
#pragma unroll
            for (int q = 0; q < 4; q++) acc[mt][nt][q] = 0.0f;

    gemm_tile_body(Aghi, Aglo, Bchi, Bclo, smem, row0, j0, acc);

    int wid = threadIdx.x >> 5, lane = threadIdx.x & 31;
    int g = lane >> 2, t = lane & 3;
    int rowg = wid & 3, colg = wid >> 2;
    // acc = gi (pairs with b_ih); g_gh buffer = gh (pairs with b_hh)
#pragma unroll
    for (int mt = 0; mt < 2; mt++) {
        int rbase = row0 + rowg * 32 + mt * 16 + g;
#pragma unroll
        for (int sub = 0; sub < 2; sub++) {
            int jj = j0 + colg * 16 + sub * 8 + t * 2;
            float2 bihr = *(const float2*)&b_ih[jj];
            float2 bihz = *(const float2*)&b_ih[128 + jj];
            float2 bihn = *(const float2*)&b_ih[256 + jj];
            float2 bhhr = *(const float2*)&b_hh[jj];
            float2 bhhz = *(const float2*)&b_hh[128 + jj];
            float2 bhhn = *(const float2*)&b_hh[256 + jj];
#pragma unroll
            for (int q = 0; q < 2; q++) {
                int rr = rbase + q * 8;
                float2 ghr2 = *(const float2*)&g_gh[(size_t)rr * H3 + jj];
                float2 ghz2 = *(const float2*)&g_gh[(size_t)rr * H3 + 128 + jj];
                float2 ghn2 = *(const float2*)&g_gh[(size_t)rr * H3 + 256 + jj];
                float2 hp  = *(const float2*)&hprev[(size_t)rr * HH + jj];
                float hn[2];
#pragma unroll
                for (int c = 0; c < 2; c++) {
                    float gir = acc[mt][sub][q * 2 + c];
                    float giz = acc[mt][2 + sub][q * 2 + c];
                    float gin = acc[mt][4 + sub][q * 2 + c];
                    float ghr = (c == 0) ? ghr2.x : ghr2.y;
                    float ghz = (c == 0) ? ghz2.x : ghz2.y;
                    float ghn = (c == 0) ? ghn2.x : ghn2.y;
                    float bir = (c == 0) ? bihr.x : bihr.y;
                    float biz = (c == 0) ? bihz.x : bihz.y;
                    float bin = (c == 0) ? bihn.x : bihn.y;
                    float bhr = (c == 0) ? bhhr.x : bhhr.y;
                    float bhz = (c == 0) ? bhhz.x : bhhz.y;
                    float bhn = (c == 0) ? bhhn.x : bhhn.y;
                    float hpc = (c == 0) ? hp.x : hp.y;
                    float rv = sigmoidf_(gir + bir + ghr + bhr);
                    float zv = sigmoidf_(giz + biz + ghz + bhz);
                    float nv = tanhf(gin + bin + rv * (ghn + bhn));
                    hn[c] = (1.0f - zv) * nv + zv * hpc;
                }
                float2 ho; ho.x = hn[0]; ho.y = hn[1];
                *(float2*)&hout[(size_t)rr * HH + jj] = ho;
                __nv_bfloat16 hi0 = __float2bfloat16(hn[0]);
                __nv_bfloat16 hi1 = __float2bfloat16(hn[1]);
                __nv_bfloat162 hv, lv;
                hv.x = hi0; hv.y = hi1;
                lv.x = __float2bfloat16(hn[0] - __bfloat162float(hi0));
                lv.y = __float2bfloat16(hn[1] - __bfloat162float(hi1));
                *(__nv_bfloat162*)&houthi[(size_t)rr * HH + jj] = hv;
                *(__nv_bfloat162*)&houtlo[(size_t)rr * HH + jj] = lv;
            }
        }
    }
}

// ---------------- readout ----------------
__global__ void readout_kernel(const float* __restrict__ l1w, const float* __restrict__ l1b,
                               const float* __restrict__ l2w, const float* __restrict__ l2b,
                               const int* __restrict__ batch, const float* __restrict__ h,
                               float* __restrict__ out_mu, float* __restrict__ out_sigma) {
    int gt = blockIdx.x * blockDim.x + threadIdx.x;
    int n = gt >> 5;
    int lane = gt & 31;
    if (n >= NN) return;
    float s1 = 0.0f, s2 = 0.0f;
#pragma unroll
    for (int k = lane; k < HH; k += 32) {
        float v = fmaxf(h[(size_t)n * HH + k], 0.0f);
        s1 += v * l1w[k];
        s2 += v * l2w[k];
    }
#pragma unroll
    for (int o = 16; o; o >>= 1) {
        s1 += __shfl_down_sync(0xffffffffu, s1, o);
        s2 += __shfl_down_sync(0xffffffffu, s2, o);
    }
    if (lane == 0) {
        float mu = s1 + l1b[0];
        float sp = s2 + l2b[0];
        float sigma = fmaxf(sp, 0.0f) + log1pf(expf(-fabsf(sp)));
        out_mu[n] = mu;
        out_sigma[n] = sigma;
        atomicAdd(&g_mu_all[batch[n]], mu);
        atomicAdd(&g_sig_all[batch[n]], sigma);
    }
}

__global__ void correct_kernel(const int* __restrict__ batch,
                               const float* __restrict__ out_mu, const float* __restrict__ out_sigma,
                               float* __restrict__ out_mu_c) {
    int n = blockIdx.x * blockDim.x + threadIdx.x;
    if (n >= NN) return;
    int b = batch[n];
    out_mu_c[n] = out_mu[n] - g_mu_all[b] * (out_sigma[n] / g_sig_all[b]);
}

// ---------------- launch ----------------
extern "C" void kernel_launch(void* const* d_in, const int* in_sizes, int n_in,
                              void* d_out, int out_size) {
    const float* x      = (const float*)d_in[0];
    const int*   edge   = (const int*)d_in[1];
    const int*   batch  = (const int*)d_in[2];
    const float* lin0_w = (const float*)d_in[3];
    const float* ggc_w  = (const float*)d_in[4];
    const float* w_ih   = (const float*)d_in[5];
    const float* w_hh   = (const float*)d_in[6];
    const float* b_ih   = (const float*)d_in[7];
    const float* b_hh   = (const float*)d_in[8];
    const float* l1w    = (const float*)d_in[9];
    const float* l1b    = (const float*)d_in[10];
    const float* l2w    = (const float*)d_in[11];
    const float* l2b    = (const float*)d_in[12];

    float* out       = (float*)d_out;
    float* out_mu_c  = out;
    float* out_x1    = out + NN;
    float* out_sigma = out + NN + NN * EMB;
    float* out_mu    = out + NN + NN * EMB + NN;

    const int* src = edge;
    const int* dst = edge + EE;

    float *ph0, *ph1, *pcl;
    __nv_bfloat16 *phhi0, *phlo0, *phhi1, *phlo1, *paghi, *paglo, *pclThi, *pclTlo, *pwhhhi, *pwhhlo;
    cudaGetSymbolAddress((void**)&ph0,    g_h0);
    cudaGetSymbolAddress((void**)&ph1,    g_h1);
    cudaGetSymbolAddress((void**)&pcl,    g_cl);
    cudaGetSymbolAddress((void**)&phhi0,  g_hhi0);
    cudaGetSymbolAddress((void**)&phlo0,  g_hlo0);
    cudaGetSymbolAddress((void**)&phhi1,  g_hhi1);
    cudaGetSymbolAddress((void**)&phlo1,  g_hlo1);
    cudaGetSymbolAddress((void**)&paghi,  g_aghi);
    cudaGetSymbolAddress((void**)&paglo,  g_aglo);
    cudaGetSymbolAddress((void**)&pclThi, g_clT_hi);
    cudaGetSymbolAddress((void**)&pclTlo, g_clT_lo);
    cudaGetSymbolAddress((void**)&pwhhhi, g_whh_hi);
    cudaGetSymbolAddress((void**)&pwhhlo, g_whh_lo);

    cudaFuncSetAttribute(combined_gh_agg_kernel, cudaFuncAttributeMaxDynamicSharedMemorySize, GSMEM);
    cudaFuncSetAttribute(gates_kernel, cudaFuncAttributeMaxDynamicSharedMemorySize, GSMEM);

    zero_deg_kernel<<<(NN + 255) / 256, 256>>>();
    zero_graph_kernel<<<1, GG>>>();
    count_deg_kernel<<<(EE + 255) / 256, 256>>>(dst);
    scan1_kernel<<<NBLK, SCAN_B>>>();
    scan2_kernel<<<1, 32>>>();
    scan3_kernel<<<(NN + 255) / 256, 256>>>();
    fill_csr_kernel<<<(EE + 255) / 256, 256>>>(src, dst);

    lin0_kernel<<<(NN + 3) / 4, 256>>>(x, lin0_w, out_x1);

    {
        dim3 gcl((H3 + 63) / 64, (HH + 63) / 64);
        for (int l = 0; l < LL; l++)
            gemm_kernel<true><<<gcl, 256>>>(ggc_w + l * HH * HH, w_ih, pcl + l * HH * H3, HH, H3, HH);
        conv_cl_kernel<<<(LL * H3 * HH + 255) / 256, 256>>>();
        conv_whh_kernel<<<(H3 * HH + 255) / 256, 256>>>(w_hh);
    }

    dim3 cgrid(4, TOT_BY);
    dim3 ggrid(4, GEMM_BY);
    for (int l = 0; l < LL; l++) {
        const float* hcur = (l & 1) ? ph1 : ph0;
        float* hnext      = (l & 1) ? ph0 : ph1;
        __nv_bfloat16* hhicur = (l & 1) ? phhi1 : phhi0;
        __nv_bfloat16* hlocur = (l & 1) ? phlo1 : phlo0;
        __nv_bfloat16* hhinxt = (l & 1) ? phhi0 : phhi1;
        __nv_bfloat16* hlonxt = (l & 1) ? phlo0 : phlo1;

        combined_gh_agg_kernel<<<cgrid, 256, GSMEM>>>(hhicur, hlocur, pwhhhi, pwhhlo,
                                                      hcur, paghi, paglo);
        gates_kernel<<<ggrid, 256, GSMEM>>>(paghi, paglo,
                                            pclThi + l * H3 * HH, pclTlo + l * H3 * HH,
                                            b_ih, b_hh, hcur,
                                            hnext, hhinxt, hlonxt);
    }

    readout_kernel<<<(NN * 32 + 255) / 256, 256>>>(l1w, l1b, l2w, l2b, batch, ph0, out_mu, out_sigma);
    correct_kernel<<<(NN + 255) / 256, 256>>>(batch, out_mu, out_sigma, out_mu_c);
}

// round 15
// speedup vs baseline: 1.2804x; 1.2804x over previous
#include <cuda_runtime.h>
#include <cuda_bf16.h>
#include <cstdint>
#include <math.h>

#define NN    100000
#define NPAD  100096
#define EE    1600000
#define FIN   27
#define EMB   64
#define HH    128
#define H3    384
#define LL    4
#define GG    512
#define SCAN_B 512
#define NBLK  ((NN + SCAN_B - 1) / SCAN_B)

// ---------------- device scratch ----------------
__device__ float g_h0[NPAD * HH];
__device__ float g_h1[NPAD * HH];
__device__ __nv_bfloat16 g_hhi0[NPAD * HH];
__device__ __nv_bfloat16 g_hlo0[NPAD * HH];
__device__ __nv_bfloat16 g_hhi1[NPAD * HH];
__device__ __nv_bfloat16 g_hlo1[NPAD * HH];
__device__ __nv_bfloat16 g_aghi[NPAD * HH];
__device__ __nv_bfloat16 g_aglo[NPAD * HH];
__device__ float g_gi[NPAD * H3];
__device__ float g_cl[LL * HH * H3];
__device__ __nv_bfloat16 g_clT_hi[LL * H3 * HH];
__device__ __nv_bfloat16 g_clT_lo[LL * H3 * HH];
__device__ __nv_bfloat16 g_whh_hi[H3 * HH];
__device__ __nv_bfloat16 g_whh_lo[H3 * HH];
__device__ int   g_deg[NN];
__device__ int   g_rowptr[NN];
__device__ int   g_cursor[NN];
__device__ int   g_csr[EE];
__device__ int   g_bsums[NBLK];
__device__ float g_mu_all[GG];
__device__ float g_sig_all[GG];

__device__ __forceinline__ float sigmoidf_(float v) {
    return 1.0f / (1.0f + expf(-v));
}

__device__ __forceinline__ void mma16816(float* d, const uint32_t* a, const uint32_t* b) {
    asm volatile(
        "mma.sync.aligned.m16n8k16.row.col.f32.bf16.bf16.f32 {%0,%1,%2,%3}, {%4,%5,%6,%7}, {%8,%9}, {%0,%1,%2,%3};"
        : "+f"(d[0]), "+f"(d[1]), "+f"(d[2]), "+f"(d[3])
        : "r"(a[0]), "r"(a[1]), "r"(a[2]), "r"(a[3]), "r"(b[0]), "r"(b[1]));
}

// swizzled smem: row r (pitch 256B), 16B chunk ch stored at (ch ^ (r&7))
__device__ __forceinline__ uint32_t lds_frag(const char* base, int r, int kch, int t) {
    return *(const uint32_t*)(base + r * 256 + (((kch) ^ (r & 7)) << 4) + t * 4);
}

// ---------------- CSR build ----------------
__global__ void zero_deg_kernel() {
    int i = blockIdx.x * blockDim.x + threadIdx.x;
    if (i < NN) g_deg[i] = 0;
}
__global__ void zero_graph_kernel() {
    int i = threadIdx.x;
    if (i < GG) { g_mu_all[i] = 0.0f; g_sig_all[i] = 0.0f; }
}
__global__ void count_deg_kernel(const int* __restrict__ dst) {
    int e = blockIdx.x * blockDim.x + threadIdx.x;
    if (e < EE) atomicAdd(&g_deg[dst[e]], 1);
}
__global__ void scan1_kernel() {
    __shared__ int s[SCAN_B];
    int i = blockIdx.x * SCAN_B + threadIdx.x;
    int v = (i < NN) ? g_deg[i] : 0;
    s[threadIdx.x] = v;
    __syncthreads();
    for (int off = 1; off < SCAN_B; off <<= 1) {
        int t = 0;
        if (threadIdx.x >= off) t = s[threadIdx.x - off];
        __syncthreads();
        s[threadIdx.x] += t;
        __syncthreads();
    }
    if (i < NN) g_rowptr[i] = s[threadIdx.x] - v;
    if (threadIdx.x == SCAN_B - 1) g_bsums[blockIdx.x] = s[SCAN_B - 1];
}
__global__ void scan2_kernel() {
    if (threadIdx.x == 0) {
        int run = 0;
        for (int b = 0; b < NBLK; b++) { int t = g_bsums[b]; g_bsums[b] = run; run += t; }
    }
}
__global__ void scan3_kernel() {
    int i = blockIdx.x * blockDim.x + threadIdx.x;
    if (i < NN) {
        int v = g_rowptr[i] + g_bsums[i / SCAN_B];
        g_rowptr[i] = v;
        g_cursor[i] = v;
    }
}
__global__ void fill_csr_kernel(const int* __restrict__ src, const int* __restrict__ dst) {
    int e = blockIdx.x * blockDim.x + threadIdx.x;
    if (e < EE) {
        int p = atomicAdd(&g_cursor[dst[e]], 1);
        g_csr[p] = src[e];
    }
}

// ---------------- lin0 ----------------
__global__ void lin0_kernel(const float* __restrict__ x, const float* __restrict__ w,
                            float* __restrict__ out_x1) {
    int local = threadIdx.x >> 6;
    int j     = threadIdx.x & 63;
    int node  = blockIdx.x * 4 + local;
    __shared__ float xs[4][FIN];
    if (node < NN && j < FIN) xs[local][j] = x[node * FIN + j];
    __syncthreads();
    if (node >= NN) return;
    float acc = 0.0f;
#pragma unroll
    for (int k = 0; k < FIN; k++) acc += xs[local][k] * w[k * EMB + j];
    float v = sigmoidf_(acc);
    out_x1[node * EMB + j] = v;
    g_h0[node * HH + j] = v;
    g_h0[node * HH + EMB + j] = 0.0f;
    __nv_bfloat16 hi = __float2bfloat16(v);
    __nv_bfloat16 lo = __float2bfloat16(v - __bfloat162float(hi));
    g_hhi0[node * HH + j] = hi;
    g_hlo0[node * HH + j] = lo;
    g_hhi0[node * HH + EMB + j] = __float2bfloat16(0.0f);
    g_hlo0[node * HH + EMB + j] = __float2bfloat16(0.0f);
}

// ---------------- small fp32 GEMM (weight precompute only) ----------------
template <bool BT>
__global__ void gemm_kernel(const float* __restrict__ A, const float* __restrict__ B,
                            float* __restrict__ C, int M, int Ncol, int K) {
    const int BM = 64, BN = 64, BK = 16;
    __shared__ float As[BK][BM];
    __shared__ float Bs[BK][BN];
    int t  = threadIdx.x;
    int tx = t & 15, ty = t >> 4;
    int row0 = blockIdx.y * BM, col0 = blockIdx.x * BN;
    float acc[4][4] = {};
    for (int k0 = 0; k0 < K; k0 += BK) {
#pragma unroll
        for (int i = 0; i < 4; i++) {
            int idx = t + i * 256;
            int r = idx >> 4, c = idx & 15;
            int gr = row0 + r;
            As[c][r] = (gr < M) ? A[gr * K + k0 + c] : 0.0f;
        }
#pragma unroll
        for (int i = 0; i < 4; i++) {
            int idx = t + i * 256;
            if (BT) {
                int j = idx >> 4, c = idx & 15;
                Bs[c][j] = B[(col0 + j) * K + k0 + c];
            } else {
                int r = idx >> 6, j = idx & 63;
                Bs[r][j] = B[(k0 + r) * Ncol + col0 + j];
            }
        }
        __syncthreads();
#pragma unroll
        for (int k = 0; k < BK; k++) {
            float4 a4 = *(const float4*)&As[k][ty * 4];
            float4 b4 = *(const float4*)&Bs[k][tx * 4];
            float av[4]; float bv[4];
            av[0] = a4.x; av[1] = a4.y; av[2] = a4.z; av[3] = a4.w;
            bv[0] = b4.x; bv[1] = b4.y; bv[2] = b4.z; bv[3] = b4.w;
#pragma unroll
            for (int i = 0; i < 4; i++)
#pragma unroll
                for (int j = 0; j < 4; j++) acc[i][j] += av[i] * bv[j];
        }
        __syncthreads();
    }
#pragma unroll
    for (int i = 0; i < 4; i++) {
        int gr = row0 + ty * 4 + i;
        if (gr < M) {
#pragma unroll
            for (int j = 0; j < 4; j++) C[gr * Ncol + col0 + tx * 4 + j] = acc[i][j];
        }
    }
}

// ---------------- weight prep ----------------
__global__ void conv_cl_kernel() {
    int idx = blockIdx.x * blockDim.x + threadIdx.x;
    if (idx >= LL * H3 * HH) return;
    int l = idx / (H3 * HH);
    int rem = idx - l * H3 * HH;
    int n = rem >> 7, k = rem & 127;
    float v = g_cl[l * HH * H3 + k * H3 + n];
    __nv_bfloat16 hi = __float2bfloat16(v);
    g_clT_hi[idx] = hi;
    g_clT_lo[idx] = __float2bfloat16(v - __bfloat162float(hi));
}
__global__ void conv_whh_kernel(const float* __restrict__ w) {
    int idx = blockIdx.x * blockDim.x + threadIdx.x;
    if (idx >= H3 * HH) return;
    float v = w[idx];
    __nv_bfloat16 hi = __float2bfloat16(v);
    g_whh_hi[idx] = hi;
    g_whh_lo[idx] = __float2bfloat16(v - __bfloat162float(hi));
}

// ---------------- CSR gather aggregation: warp per node, fp32 float4, unroll 4 ----------------
__global__ void agg_kernel(const float* __restrict__ h) {
    int wid = threadIdx.x >> 5, lane = threadIdx.x & 31;
    int n = blockIdx.x * 8 + wid;
    if (n >= NN) return;
    int s0 = g_rowptr[n];
    int d  = g_deg[n];
    float4 acc; acc.x = 0.0f; acc.y = 0.0f; acc.z = 0.0f; acc.w = 0.0f;
    int e = 0;
    for (; e + 4 <= d; e += 4) {
        int s1 = g_csr[s0 + e];
        int s2 = g_csr[s0 + e + 1];
        int s3 = g_csr[s0 + e + 2];
        int s4 = g_csr[s0 + e + 3];
        float4 v1 = *(const float4*)&h[(size_t)s1 * HH + lane * 4];
        float4 v2 = *(const float4*)&h[(size_t)s2 * HH + lane * 4];
        float4 v3 = *(const float4*)&h[(size_t)s3 * HH + lane * 4];
        float4 v4 = *(const float4*)&h[(size_t)s4 * HH + lane * 4];
        acc.x += (v1.x + v2.x) + (v3.x + v4.x);
        acc.y += (v1.y + v2.y) + (v3.y + v4.y);
        acc.z += (v1.z + v2.z) + (v3.z + v4.z);
        acc.w += (v1.w + v2.w) + (v3.w + v4.w);
    }
    for (; e < d; e++) {
        int s1 = g_csr[s0 + e];
        float4 v1 = *(const float4*)&h[(size_t)s1 * HH + lane * 4];
        acc.x += v1.x; acc.y += v1.y; acc.z += v1.z; acc.w += v1.w;
    }
    float vals[4]; vals[0] = acc.x; vals[1] = acc.y; vals[2] = acc.z; vals[3] = acc.w;
    __nv_bfloat162 hi01, hi23, lo01, lo23;
    __nv_bfloat16 h0 = __float2bfloat16(vals[0]);
    __nv_bfloat16 h1 = __float2bfloat16(vals[1]);
    __nv_bfloat16 h2 = __float2bfloat16(vals[2]);
    __nv_bfloat16 h3 = __float2bfloat16(vals[3]);
    hi01.x = h0; hi01.y = h1; hi23.x = h2; hi23.y = h3;
    lo01.x = __float2bfloat16(vals[0] - __bfloat162float(h0));
    lo01.y = __float2bfloat16(vals[1] - __bfloat162float(h1));
    lo23.x = __float2bfloat16(vals[2] - __bfloat162float(h2));
    lo23.y = __float2bfloat16(vals[3] - __bfloat162float(h3));
    *(__nv_bfloat162*)&g_aghi[(size_t)n * HH + lane * 4]     = hi01;
    *(__nv_bfloat162*)&g_aghi[(size_t)n * HH + lane * 4 + 2] = hi23;
    *(__nv_bfloat162*)&g_aglo[(size_t)n * HH + lane * 4]     = lo01;
    *(__nv_bfloat162*)&g_aglo[(size_t)n * HH + lane * 4 + 2] = lo23;
}

// ---------------- gate-aligned bf16 split GEMM (R8 structure) ----------------
// MODE 0: C = A@B^T -> write gi.  MODE 1: compute gh, fuse GRU gates, write h + hhi/hlo.
// KSTEPS: number of K=16 steps (4 for layer 0 where h cols 64-127 are exactly zero; 8 otherwise).
// grid = (4, NPAD/128), 256 threads, 2 CTAs/SM.
#define SM_A_HI 0
#define SM_A_LO 32768
#define SM_B_HI 65536
#define SM_B_LO 90112
#define GSMEM   114688

template <int MODE, int KSTEPS>
__global__ void __launch_bounds__(256, 2)
mma_tile_kernel(const __nv_bfloat16* __restrict__ Ahi, const __nv_bfloat16* __restrict__ Alo,
                const __nv_bfloat16* __restrict__ Bhi, const __nv_bfloat16* __restrict__ Blo,
                float* __restrict__ gi,
                const float* __restrict__ b_ih, const float* __restrict__ b_hh,
                const float* __restrict__ hprev,
                float* __restrict__ hout,
                __nv_bfloat16* __restrict__ houthi, __nv_bfloat16* __restrict__ houtlo) {
    extern __shared__ __align__(16) char smem[];

    const int NCH = 2 * KSTEPS;                 // 16B chunks per row used

    int tid = threadIdx.x;
    int wid = tid >> 5, lane = tid & 31;
    int g = lane >> 2, t = lane & 3;
    int rowg = wid & 3, colg = wid >> 2;
    int row0 = blockIdx.y * 128;
    int j0 = blockIdx.x * 32;

    // load A tile (128 rows x NCH chunks), swizzled
    for (int i = tid; i < 128 * NCH; i += 256) {
        int r = i / NCH, ch = i % NCH;
        int dstoff = r * 256 + ((ch ^ (r & 7)) << 4);
        *(uint4*)(smem + SM_A_HI + dstoff) = *(const uint4*)&Ahi[(size_t)(row0 + r) * 128 + ch * 8];
        *(uint4*)(smem + SM_A_LO + dstoff) = *(const uint4*)&Alo[(size_t)(row0 + r) * 128 + ch * 8];
    }
    // load B rows: br (0..95) -> n = (br/32)*128 + j0 + (br%32)
    for (int i = tid; i < 96 * NCH; i += 256) {
        int br = i / NCH, ch = i % NCH;
        int n = (br >> 5) * 128 + j0 + (br & 31);
        int dstoff = br * 256 + ((ch ^ (br & 7)) << 4);
        *(uint4*)(smem + SM_B_HI + dstoff) = *(const uint4*)&Bhi[(size_t)n * 128 + ch * 8];
        *(uint4*)(smem + SM_B_LO + dstoff) = *(const uint4*)&Blo[(size_t)n * 128 + ch * 8];
    }
    __syncthreads();

    float acc[2][6][4];
#pragma unroll
    for (int mt = 0; mt < 2; mt++)
#pragma unroll
        for (int nt = 0; nt < 6; nt++)
#pragma unroll
            for (int q = 0; q < 4; q++) acc[mt][nt][q] = 0.0f;

#pragma unroll
    for (int ks = 0; ks < KSTEPS; ks++) {
        uint32_t ah[2][4], al[2][4];
#pragma unroll
        for (int mt = 0; mt < 2; mt++) {
            int r1 = rowg * 32 + mt * 16 + g;
            int r2 = r1 + 8;
            ah[mt][0] = lds_frag(smem + SM_A_HI, r1, 2 * ks, t);
            ah[mt][1] = lds_frag(smem + SM_A_HI, r2, 2 * ks, t);
            ah[mt][2] = lds_frag(smem + SM_A_HI, r1, 2 * ks + 1, t);
            ah[mt][3] = lds_frag(smem + SM_A_HI, r2, 2 * ks + 1, t);
            al[mt][0] = lds_frag(smem + SM_A_LO, r1, 2 * ks, t);
            al[mt][1] = lds_frag(smem + SM_A_LO, r2, 2 * ks, t);
            al[mt][2] = lds_frag(smem + SM_A_LO, r1, 2 * ks + 1, t);
            al[mt][3] = lds_frag(smem + SM_A_LO, r2, 2 * ks + 1, t);
        }
#pragma unroll
        for (int nt = 0; nt < 6; nt++) {
            int br = (nt >> 1) * 32 + colg * 16 + (nt & 1) * 8 + g;
            uint32_t bh[2], bl[2];
            bh[0] = lds_frag(smem + SM_B_HI, br, 2 * ks, t);
            bh[1] = lds_frag(smem + SM_B_HI, br, 2 * ks + 1, t);
            bl[0] = lds_frag(smem + SM_B_LO, br, 2 * ks, t);
            bl[1] = lds_frag(smem + SM_B_LO, br, 2 * ks + 1, t);
#pragma unroll
            for (int mt = 0; mt < 2; mt++) {
                mma16816(acc[mt][nt], ah[mt], bh);
                mma16816(acc[mt][nt], ah[mt], bl);
                mma16816(acc[mt][nt], al[mt], bh);
            }
        }
    }

    // epilogue
#pragma unroll
    for (int mt = 0; mt < 2; mt++) {
        int rbase = row0 + rowg * 32 + mt * 16 + g;
#pragma unroll
        for (int sub = 0; sub < 2; sub++) {
            int jj = j0 + colg * 16 + sub * 8 + t * 2;   // gate col in [0,128)
            if (MODE == 0) {
#pragma unroll
                for (int g3 = 0; g3 < 3; g3++) {
                    int nt = 2 * g3 + sub;
                    float2 v0; v0.x = acc[mt][nt][0]; v0.y = acc[mt][nt][1];
                    float2 v1; v1.x = acc[mt][nt][2]; v1.y = acc[mt][nt][3];
                    *(float2*)&gi[(size_t)rbase * H3 + g3 * 128 + jj] = v0;
                    *(float2*)&gi[(size_t)(rbase + 8) * H3 + g3 * 128 + jj] = v1;
                }
            } else {
                float2 bihr = *(const float2*)&b_ih[jj];
                float2 bihz = *(const float2*)&b_ih[128 + jj];
                float2 bihn = *(const float2*)&b_ih[256 + jj];
                float2 bhhr = *(const float2*)&b_hh[jj];
                float2 bhhz = *(const float2*)&b_hh[128 + jj];
                float2 bhhn = *(const float2*)&b_hh[256 + jj];
#pragma unroll
                for (int q = 0; q < 2; q++) {
                    int rr = rbase + q * 8;
                    float2 gir = *(const float2*)&gi[(size_t)rr * H3 + jj];
                    float2 giz = *(const float2*)&gi[(size_t)rr * H3 + 128 + jj];
                    float2 gin = *(const float2*)&gi[(size_t)rr * H3 + 256 + jj];
                    float2 hp  = *(const float2*)&hprev[(size_t)rr * HH + jj];
                    float hn[2];
#pragma unroll
                    for (int c = 0; c < 2; c++) {
                        float ghr = acc[mt][sub][q * 2 + c];
                        float ghz = acc[mt][2 + sub][q * 2 + c];
                        float ghn = acc[mt][4 + sub][q * 2 + c];
                        float gir_c = (c == 0) ? gir.x : gir.y;
                        float giz_c = (c == 0) ? giz.x : giz.y;
                        float gin_c = (c == 0) ? gin.x : gin.y;
                        float bir = (c == 0) ? bihr.x : bihr.y;
                        float biz = (c == 0) ? bihz.x : bihz.y;
                        float bin = (c == 0) ? bihn.x : bihn.y;
                        float bhr = (c == 0) ? bhhr.x : bhhr.y;
                        float bhz = (c == 0) ? bhhz.x : bhhz.y;
                        float bhn = (c == 0) ? bhhn.x : bhhn.y;
                        float hpc = (c == 0) ? hp.x : hp.y;
                        float rv = sigmoidf_(gir_c + bir + ghr + bhr);
                        float zv = sigmoidf_(giz_c + biz + ghz + bhz);
                        float nv = tanhf(gin_c + bin + rv * (ghn + bhn));
                        hn[c] = (1.0f - zv) * nv + zv * hpc;
                    }
                    float2 ho; ho.x = hn[0]; ho.y = hn[1];
                    *(float2*)&hout[(size_t)rr * HH + jj] = ho;
                    __nv_bfloat16 hi0 = __float2bfloat16(hn[0]);
                    __nv_bfloat16 hi1 = __float2bfloat16(hn[1]);
                    __nv_bfloat162 hv, lv;
                    hv.x = hi0; hv.y = hi1;
                    lv.x = __float2bfloat16(hn[0] - __bfloat162float(hi0));
                    lv.y = __float2bfloat16(hn[1] - __bfloat162float(hi1));
                    *(__nv_bfloat162*)&houthi[(size_t)rr * HH + jj] = hv;
                    *(__nv_bfloat162*)&houtlo[(size_t)rr * HH + jj] = lv;
                }
            }
        }
    }
}

// ---------------- readout ----------------
__global__ void readout_kernel(const float* __restrict__ l1w, const float* __restrict__ l1b,
                               const float* __restrict__ l2w, const float* __restrict__ l2b,
                               const int* __restrict__ batch, const float* __restrict__ h,
                               float* __restrict__ out_mu, float* __restrict__ out_sigma) {
    int gt = blockIdx.x * blockDim.x + threadIdx.x;
    int n = gt >> 5;
    int lane = gt & 31;
    if (n >= NN) return;
    float s1 = 0.0f, s2 = 0.0f;
#pragma unroll
    for (int k = lane; k < HH; k += 32) {
        float v = fmaxf(h[(size_t)n * HH + k], 0.0f);
        s1 += v * l1w[k];
        s2 += v * l2w[k];
    }
#pragma unroll
    for (int o = 16; o; o >>= 1) {
        s1 += __shfl_down_sync(0xffffffffu, s1, o);
        s2 += __shfl_down_sync(0xffffffffu, s2, o);
    }
    if (lane == 0) {
        float mu = s1 + l1b[0];
        float sp = s2 + l2b[0];
        float sigma = fmaxf(sp, 0.0f) + log1pf(expf(-fabsf(sp)));
        out_mu[n] = mu;
        out_sigma[n] = sigma;
        atomicAdd(&g_mu_all[batch[n]], mu);
        atomicAdd(&g_sig_all[batch[n]], sigma);
    }
}

__global__ void correct_kernel(const int* __restrict__ batch,
                               const float* __restrict__ out_mu, const float* __restrict__ out_sigma,
                               float* __restrict__ out_mu_c) {
    int n = blockIdx.x * blockDim.x + threadIdx.x;
    if (n >= NN) return;
    int b = batch[n];
    out_mu_c[n] = out_mu[n] - g_mu_all[b] * (out_sigma[n] / g_sig_all[b]);
}

// ---------------- launch ----------------
extern "C" void kernel_launch(void* const* d_in, const int* in_sizes, int n_in,
                              void* d_out, int out_size) {
    const float* x      = (const float*)d_in[0];
    const int*   edge   = (const int*)d_in[1];
    const int*   batch  = (const int*)d_in[2];
    const float* lin0_w = (const float*)d_in[3];
    const float* ggc_w  = (const float*)d_in[4];
    const float* w_ih   = (const float*)d_in[5];
    const float* w_hh   = (const float*)d_in[6];
    const float* b_ih   = (const float*)d_in[7];
    const float* b_hh   = (const float*)d_in[8];
    const float* l1w    = (const float*)d_in[9];
    const float* l1b    = (const float*)d_in[10];
    const float* l2w    = (const float*)d_in[11];
    const float* l2b    = (const float*)d_in[12];

    float* out       = (float*)d_out;
    float* out_mu_c  = out;
    float* out_x1    = out + NN;
    float* out_sigma = out + NN + NN * EMB;
    float* out_mu    = out + NN + NN * EMB + NN;

    const int* src = edge;
    const int* dst = edge + EE;

    float *ph0, *ph1, *pgi, *pcl;
    __nv_bfloat16 *phhi0, *phlo0, *phhi1, *phlo1, *paghi, *paglo, *pclThi, *pclTlo, *pwhhhi, *pwhhlo;
    cudaGetSymbolAddress((void**)&ph0,    g_h0);
    cudaGetSymbolAddress((void**)&ph1,    g_h1);
    cudaGetSymbolAddress((void**)&pgi,    g_gi);
    cudaGetSymbolAddress((void**)&pcl,    g_cl);
    cudaGetSymbolAddress((void**)&phhi0,  g_hhi0);
    cudaGetSymbolAddress((void**)&phlo0,  g_hlo0);
    cudaGetSymbolAddress((void**)&phhi1,  g_hhi1);
    cudaGetSymbolAddress((void**)&phlo1,  g_hlo1);
    cudaGetSymbolAddress((void**)&paghi,  g_aghi);
    cudaGetSymbolAddress((void**)&paglo,  g_aglo);
    cudaGetSymbolAddress((void**)&pclThi, g_clT_hi);
    cudaGetSymbolAddress((void**)&pclTlo, g_clT_lo);
    cudaGetSymbolAddress((void**)&pwhhhi, g_whh_hi);
    cudaGetSymbolAddress((void**)&pwhhlo, g_whh_lo);

    cudaFuncSetAttribute((const void*)mma_tile_kernel<0, 8>, cudaFuncAttributeMaxDynamicSharedMemorySize, GSMEM);
    cudaFuncSetAttribute((const void*)mma_tile_kernel<1, 8>, cudaFuncAttributeMaxDynamicSharedMemorySize, GSMEM);
    cudaFuncSetAttribute((const void*)mma_tile_kernel<0, 4>, cudaFuncAttributeMaxDynamicSharedMemorySize, GSMEM);
    cudaFuncSetAttribute((const void*)mma_tile_kernel<1, 4>, cudaFuncAttributeMaxDynamicSharedMemorySize, GSMEM);

    zero_deg_kernel<<<(NN + 255) / 256, 256>>>();
    zero_graph_kernel<<<1, GG>>>();
    count_deg_kernel<<<(EE + 255) / 256, 256>>>(dst);
    scan1_kernel<<<NBLK, SCAN_B>>>();
    scan2_kernel<<<1, 32>>>();
    scan3_kernel<<<(NN + 255) / 256, 256>>>();
    fill_csr_kernel<<<(EE + 255) / 256, 256>>>(src, dst);

    lin0_kernel<<<(NN + 3) / 4, 256>>>(x, lin0_w, out_x1);

    {
        dim3 gcl((H3 + 63) / 64, (HH + 63) / 64);
        for (int l = 0; l < LL; l++)
            gemm_kernel<true><<<gcl, 256>>>(ggc_w + l * HH * HH, w_ih, pcl + l * HH * H3, HH, H3, HH);
        conv_cl_kernel<<<(LL * H3 * HH + 255) / 256, 256>>>();
        conv_whh_kernel<<<(H3 * HH + 255) / 256, 256>>>(w_hh);
    }

    dim3 ggrid(4, NPAD / 128);
    for (int l = 0; l < LL; l++) {
        const float* hcur = (l & 1) ? ph1 : ph0;
        float* hnext      = (l & 1) ? ph0 : ph1;
        __nv_bfloat16* hhicur = (l & 1) ? phhi1 : phhi0;
        __nv_bfloat16* hlocur = (l & 1) ? phlo1 : phlo0;
        __nv_bfloat16* hhinxt = (l & 1) ? phhi0 : phhi1;
        __nv_bfloat16* hlonxt = (l & 1) ? phlo0 : phlo1;

        agg_kernel<<<(NN + 7) / 8, 256>>>(hcur);
        if (l == 0) {
            // layer 0: h cols 64-127 are exactly zero -> K=64 (4 ksteps), exact
            mma_tile_kernel<0, 4><<<ggrid, 256, GSMEM>>>(paghi, paglo,
                                                         pclThi + l * H3 * HH, pclTlo + l * H3 * HH,
                                                         pgi, nullptr, nullptr, nullptr,
                                                         nullptr, nullptr, nullptr);
            mma_tile_kernel<1, 4><<<ggrid, 256, GSMEM>>>(hhicur, hlocur, pwhhhi, pwhhlo,
                                                         pgi, b_ih, b_hh, hcur,
                                                         hnext, hhinxt, hlonxt);
        } else {
            mma_tile_kernel<0, 8><<<ggrid, 256, GSMEM>>>(paghi, paglo,
                                                         pclThi + l * H3 * HH, pclTlo + l * H3 * HH,
                                                         pgi, nullptr, nullptr, nullptr,
                                                         nullptr, nullptr, nullptr);
            mma_tile_kernel<1, 8><<<ggrid, 256, GSMEM>>>(hhicur, hlocur, pwhhhi, pwhhlo,
                                                         pgi, b_ih, b_hh, hcur,
                                                         hnext, hhinxt, hlonxt);
        }
        gru_unused:;
    }

    readout_kernel<<<(NN * 32 + 255) / 256, 256>>>(l1w, l1b, l2w, l2b, batch, ph0, out_mu, out_sigma);
    correct_kernel<<<(NN + 255) / 256, 256>>>(batch, out_mu, out_sigma, out_mu_c);
}

// round 17
// speedup vs baseline: 1.3512x; 1.0553x over previous
#include <cuda_runtime.h>
#include <cuda_bf16.h>
#include <cuda_fp16.h>
#include <cstdint>
#include <math.h>

#define NN    100000
#define NPAD  100096
#define EE    1600000
#define FIN   27
#define EMB   64
#define HH    128
#define H3    384
#define LL    4
#define GG    512
#define SCAN_B 512
#define NBLK  ((NN + SCAN_B - 1) / SCAN_B)

// ---------------- device scratch ----------------
__device__ float g_h0[NPAD * HH];
__device__ float g_h1[NPAD * HH];
__device__ __nv_bfloat16 g_hhi0[NPAD * HH];
__device__ __nv_bfloat16 g_hlo0[NPAD * HH];
__device__ __nv_bfloat16 g_hhi1[NPAD * HH];
__device__ __nv_bfloat16 g_hlo1[NPAD * HH];
__device__ __nv_bfloat16 g_aghi[NPAD * HH];
__device__ __nv_bfloat16 g_aglo[NPAD * HH];
__device__ __half g_gi[NPAD * H3];
__device__ float g_cl[LL * HH * H3];
__device__ __nv_bfloat16 g_clT_hi[LL * H3 * HH];
__device__ __nv_bfloat16 g_clT_lo[LL * H3 * HH];
__device__ __nv_bfloat16 g_whh_hi[H3 * HH];
__device__ __nv_bfloat16 g_whh_lo[H3 * HH];
__device__ int   g_deg[NN];
__device__ int   g_rowptr[NN];
__device__ int   g_cursor[NN];
__device__ int   g_csr[EE];
__device__ int   g_bsums[NBLK];
__device__ float g_mu_all[GG];
__device__ float g_sig_all[GG];

__device__ __forceinline__ float sigmoidf_(float v) {
    return 1.0f / (1.0f + expf(-v));
}

__device__ __forceinline__ void mma16816(float* d, const uint32_t* a, const uint32_t* b) {
    asm volatile(
        "mma.sync.aligned.m16n8k16.row.col.f32.bf16.bf16.f32 {%0,%1,%2,%3}, {%4,%5,%6,%7}, {%8,%9}, {%0,%1,%2,%3};"
        : "+f"(d[0]), "+f"(d[1]), "+f"(d[2]), "+f"(d[3])
        : "r"(a[0]), "r"(a[1]), "r"(a[2]), "r"(a[3]), "r"(b[0]), "r"(b[1]));
}

// swizzled smem: row r (pitch 256B), 16B chunk ch stored at (ch ^ (r&7))
__device__ __forceinline__ uint32_t lds_frag(const char* base, int r, int kch, int t) {
    return *(const uint32_t*)(base + r * 256 + (((kch) ^ (r & 7)) << 4) + t * 4);
}

// ---------------- CSR build ----------------
__global__ void zero_init_kernel() {
    int i = blockIdx.x * blockDim.x + threadIdx.x;
    if (i < NN) g_deg[i] = 0;
    if (i < GG) { g_mu_all[i] = 0.0f; g_sig_all[i] = 0.0f; }
}
__global__ void count_deg_kernel(const int* __restrict__ dst) {
    int e = blockIdx.x * blockDim.x + threadIdx.x;
    if (e < EE) atomicAdd(&g_deg[dst[e]], 1);
}
__global__ void scan1_kernel() {
    __shared__ int s[SCAN_B];
    int i = blockIdx.x * SCAN_B + threadIdx.x;
    int v = (i < NN) ? g_deg[i] : 0;
    s[threadIdx.x] = v;
    __syncthreads();
    for (int off = 1; off < SCAN_B; off <<= 1) {
        int t = 0;
        if (threadIdx.x >= off) t = s[threadIdx.x - off];
        __syncthreads();
        s[threadIdx.x] += t;
        __syncthreads();
    }
    if (i < NN) g_rowptr[i] = s[threadIdx.x] - v;
    if (threadIdx.x == SCAN_B - 1) g_bsums[blockIdx.x] = s[SCAN_B - 1];
}
__global__ void scan2_kernel() {
    if (threadIdx.x == 0) {
        int run = 0;
        for (int b = 0; b < NBLK; b++) { int t = g_bsums[b]; g_bsums[b] = run; run += t; }
    }
}
__global__ void scan3_kernel() {
    int i = blockIdx.x * blockDim.x + threadIdx.x;
    if (i < NN) {
        int v = g_rowptr[i] + g_bsums[i / SCAN_B];
        g_rowptr[i] = v;
        g_cursor[i] = v;
    }
}
__global__ void fill_csr_kernel(const int* __restrict__ src, const int* __restrict__ dst) {
    int e = blockIdx.x * blockDim.x + threadIdx.x;
    if (e < EE) {
        int p = atomicAdd(&g_cursor[dst[e]], 1);
        g_csr[p] = src[e];
    }
}

// ---------------- lin0 ----------------
__global__ void lin0_kernel(const float* __restrict__ x, const float* __restrict__ w,
                            float* __restrict__ out_x1) {
    int local = threadIdx.x >> 6;
    int j     = threadIdx.x & 63;
    int node  = blockIdx.x * 4 + local;
    __shared__ float xs[4][FIN];
    if (node < NN && j < FIN) xs[local][j] = x[node * FIN + j];
    __syncthreads();
    if (node >= NN) return;
    float acc = 0.0f;
#pragma unroll
    for (int k = 0; k < FIN; k++) acc += xs[local][k] * w[k * EMB + j];
    float v = sigmoidf_(acc);
    out_x1[node * EMB + j] = v;
    g_h0[node * HH + j] = v;
    g_h0[node * HH + EMB + j] = 0.0f;
    __nv_bfloat16 hi = __float2bfloat16(v);
    __nv_bfloat16 lo = __float2bfloat16(v - __bfloat162float(hi));
    g_hhi0[node * HH + j] = hi;
    g_hlo0[node * HH + j] = lo;
    g_hhi0[node * HH + EMB + j] = __float2bfloat16(0.0f);
    g_hlo0[node * HH + EMB + j] = __float2bfloat16(0.0f);
}

// ---------------- small fp32 GEMM (weight precompute only) ----------------
template <bool BT>
__global__ void gemm_kernel(const float* __restrict__ A, const float* __restrict__ B,
                            float* __restrict__ C, int M, int Ncol, int K) {
    const int BM = 64, BN = 64, BK = 16;
    __shared__ float As[BK][BM];
    __shared__ float Bs[BK][BN];
    int t  = threadIdx.x;
    int tx = t & 15, ty = t >> 4;
    int row0 = blockIdx.y * BM, col0 = blockIdx.x * BN;
    float acc[4][4] = {};
    for (int k0 = 0; k0 < K; k0 += BK) {
#pragma unroll
        for (int i = 0; i < 4; i++) {
            int idx = t + i * 256;
            int r = idx >> 4, c = idx & 15;
            int gr = row0 + r;
            As[c][r] = (gr < M) ? A[gr * K + k0 + c] : 0.0f;
        }
#pragma unroll
        for (int i = 0; i < 4; i++) {
            int idx = t + i * 256;
            if (BT) {
                int j = idx >> 4, c = idx & 15;
                Bs[c][j] = B[(col0 + j) * K + k0 + c];
            } else {
                int r = idx >> 6, j = idx & 63;
                Bs[r][j] = B[(k0 + r) * Ncol + col0 + j];
            }
        }
        __syncthreads();
#pragma unroll
        for (int k = 0; k < BK; k++) {
            float4 a4 = *(const float4*)&As[k][ty * 4];
            float4 b4 = *(const float4*)&Bs[k][tx * 4];
            float av[4]; float bv[4];
            av[0] = a4.x; av[1] = a4.y; av[2] = a4.z; av[3] = a4.w;
            bv[0] = b4.x; bv[1] = b4.y; bv[2] = b4.z; bv[3] = b4.w;
#pragma unroll
            for (int i = 0; i < 4; i++)
#pragma unroll
                for (int j = 0; j < 4; j++) acc[i][j] += av[i] * bv[j];
        }
        __syncthreads();
    }
#pragma unroll
    for (int i = 0; i < 4; i++) {
        int gr = row0 + ty * 4 + i;
        if (gr < M) {
#pragma unroll
            for (int j = 0; j < 4; j++) C[gr * Ncol + col0 + tx * 4 + j] = acc[i][j];
        }
    }
}

// ---------------- weight prep ----------------
__global__ void conv_cl_kernel() {
    int idx = blockIdx.x * blockDim.x + threadIdx.x;
    if (idx >= LL * H3 * HH) return;
    int l = idx / (H3 * HH);
    int rem = idx - l * H3 * HH;
    int n = rem >> 7, k = rem & 127;
    float v = g_cl[l * HH * H3 + k * H3 + n];
    __nv_bfloat16 hi = __float2bfloat16(v);
    g_clT_hi[idx] = hi;
    g_clT_lo[idx] = __float2bfloat16(v - __bfloat162float(hi));
}
__global__ void conv_whh_kernel(const float* __restrict__ w) {
    int idx = blockIdx.x * blockDim.x + threadIdx.x;
    if (idx >= H3 * HH) return;
    float v = w[idx];
    __nv_bfloat16 hi = __float2bfloat16(v);
    g_whh_hi[idx] = hi;
    g_whh_lo[idx] = __float2bfloat16(v - __bfloat162float(hi));
}

// ---------------- CSR gather aggregation: warp per node ----------------
// HALF=true: only cols 0-63 of h are nonzero (layer 0) -> float2 loads, zero upper half.
template <bool HALF>
__global__ void agg_kernel(const float* __restrict__ h) {
    int wid = threadIdx.x >> 5, lane = threadIdx.x & 31;
    int n = blockIdx.x * 8 + wid;
    if (n >= NN) return;
    int s0 = g_rowptr[n];
    int d  = g_deg[n];
    if (HALF) {
        // cols lane*2, lane*2+1 (0..63)
        float2 acc; acc.x = 0.0f; acc.y = 0.0f;
        int e = 0;
        for (; e + 4 <= d; e += 4) {
            int s1 = g_csr[s0 + e];
            int s2 = g_csr[s0 + e + 1];
            int s3 = g_csr[s0 + e + 2];
            int s4 = g_csr[s0 + e + 3];
            float2 v1 = *(const float2*)&h[(size_t)s1 * HH + lane * 2];
            float2 v2 = *(const float2*)&h[(size_t)s2 * HH + lane * 2];
            float2 v3 = *(const float2*)&h[(size_t)s3 * HH + lane * 2];
            float2 v4 = *(const float2*)&h[(size_t)s4 * HH + lane * 2];
            acc.x += (v1.x + v2.x) + (v3.x + v4.x);
            acc.y += (v1.y + v2.y) + (v3.y + v4.y);
        }
        for (; e < d; e++) {
            int s1 = g_csr[s0 + e];
            float2 v1 = *(const float2*)&h[(size_t)s1 * HH + lane * 2];
            acc.x += v1.x; acc.y += v1.y;
        }
        __nv_bfloat16 h0 = __float2bfloat16(acc.x);
        __nv_bfloat16 h1 = __float2bfloat16(acc.y);
        __nv_bfloat162 hv, lv, zv;
        hv.x = h0; hv.y = h1;
        lv.x = __float2bfloat16(acc.x - __bfloat162float(h0));
        lv.y = __float2bfloat16(acc.y - __bfloat162float(h1));
        zv.x = __float2bfloat16(0.0f); zv.y = __float2bfloat16(0.0f);
        *(__nv_bfloat162*)&g_aghi[(size_t)n * HH + lane * 2] = hv;
        *(__nv_bfloat162*)&g_aglo[(size_t)n * HH + lane * 2] = lv;
        *(__nv_bfloat162*)&g_aghi[(size_t)n * HH + 64 + lane * 2] = zv;
        *(__nv_bfloat162*)&g_aglo[(size_t)n * HH + 64 + lane * 2] = zv;
        return;
    }
    float4 acc; acc.x = 0.0f; acc.y = 0.0f; acc.z = 0.0f; acc.w = 0.0f;
    int e = 0;
    for (; e + 4 <= d; e += 4) {
        int s1 = g_csr[s0 + e];
        int s2 = g_csr[s0 + e + 1];
        int s3 = g_csr[s0 + e + 2];
        int s4 = g_csr[s0 + e + 3];
        float4 v1 = *(const float4*)&h[(size_t)s1 * HH + lane * 4];
        float4 v2 = *(const float4*)&h[(size_t)s2 * HH + lane * 4];
        float4 v3 = *(const float4*)&h[(size_t)s3 * HH + lane * 4];
        float4 v4 = *(const float4*)&h[(size_t)s4 * HH + lane * 4];
        acc.x += (v1.x + v2.x) + (v3.x + v4.x);
        acc.y += (v1.y + v2.y) + (v3.y + v4.y);
        acc.z += (v1.z + v2.z) + (v3.z + v4.z);
        acc.w += (v1.w + v2.w) + (v3.w + v4.w);
    }
    for (; e < d; e++) {
        int s1 = g_csr[s0 + e];
        float4 v1 = *(const float4*)&h[(size_t)s1 * HH + lane * 4];
        acc.x += v1.x; acc.y += v1.y; acc.z += v1.z; acc.w += v1.w;
    }
    float vals[4]; vals[0] = acc.x; vals[1] = acc.y; vals[2] = acc.z; vals[3] = acc.w;
    __nv_bfloat162 hi01, hi23, lo01, lo23;
    __nv_bfloat16 h0 = __float2bfloat16(vals[0]);
    __nv_bfloat16 h1 = __float2bfloat16(vals[1]);
    __nv_bfloat16 h2 = __float2bfloat16(vals[2]);
    __nv_bfloat16 h3 = __float2bfloat16(vals[3]);
    hi01.x = h0; hi01.y = h1; hi23.x = h2; hi23.y = h3;
    lo01.x = __float2bfloat16(vals[0] - __bfloat162float(h0));
    lo01.y = __float2bfloat16(vals[1] - __bfloat162float(h1));
    lo23.x = __float2bfloat16(vals[2] - __bfloat162float(h2));
    lo23.y = __float2bfloat16(vals[3] - __bfloat162float(h3));
    *(__nv_bfloat162*)&g_aghi[(size_t)n * HH + lane * 4]     = hi01;
    *(__nv_bfloat162*)&g_aghi[(size_t)n * HH + lane * 4 + 2] = hi23;
    *(__nv_bfloat162*)&g_aglo[(size_t)n * HH + lane * 4]     = lo01;
    *(__nv_bfloat162*)&g_aglo[(size_t)n * HH + lane * 4 + 2] = lo23;
}

// ---------------- gate-aligned bf16 split GEMM ----------------
// MODE 0: C = A@B^T -> write gi (fp16).  MODE 1: gh + fused GRU gates.
// KSTEPS: 4 for layer 0 (h cols 64-127 exactly zero), 8 otherwise.
#define SM_A_HI 0
#define SM_A_LO 32768
#define SM_B_HI 65536
#define SM_B_LO 90112
#define GSMEM   114688

template <int MODE, int KSTEPS>
__global__ void __launch_bounds__(256, 2)
mma_tile_kernel(const __nv_bfloat16* __restrict__ Ahi, const __nv_bfloat16* __restrict__ Alo,
                const __nv_bfloat16* __restrict__ Bhi, const __nv_bfloat16* __restrict__ Blo,
                __half* __restrict__ gi,
                const float* __restrict__ b_ih, const float* __restrict__ b_hh,
                const float* __restrict__ hprev,
                float* __restrict__ hout,
                __nv_bfloat16* __restrict__ houthi, __nv_bfloat16* __restrict__ houtlo) {
    extern __shared__ __align__(16) char smem[];

    const int NCH = 2 * KSTEPS;

    int tid = threadIdx.x;
    int wid = tid >> 5, lane = tid & 31;
    int g = lane >> 2, t = lane & 3;
    int rowg = wid & 3, colg = wid >> 2;
    int row0 = blockIdx.y * 128;
    int j0 = blockIdx.x * 32;

    for (int i = tid; i < 128 * NCH; i += 256) {
        int r = i / NCH, ch = i % NCH;
        int dstoff = r * 256 + ((ch ^ (r & 7)) << 4);
        *(uint4*)(smem + SM_A_HI + dstoff) = *(const uint4*)&Ahi[(size_t)(row0 + r) * 128 + ch * 8];
        *(uint4*)(smem + SM_A_LO + dstoff) = *(const uint4*)&Alo[(size_t)(row0 + r) * 128 + ch * 8];
    }
    for (int i = tid; i < 96 * NCH; i += 256) {
        int br = i / NCH, ch = i % NCH;
        int n = (br >> 5) * 128 + j0 + (br & 31);
        int dstoff = br * 256 + ((ch ^ (br & 7)) << 4);
        *(uint4*)(smem + SM_B_HI + dstoff) = *(const uint4*)&Bhi[(size_t)n * 128 + ch * 8];
        *(uint4*)(smem + SM_B_LO + dstoff) = *(const uint4*)&Blo[(size_t)n * 128 + ch * 8];
    }
    __syncthreads();

    float acc[2][6][4];
#pragma unroll
    for (int mt = 0; mt < 2; mt++)
#pragma unroll
        for (int nt = 0; nt < 6; nt++)
#pragma unroll
            for (int q = 0; q < 4; q++) acc[mt][nt][q] = 0.0f;

#pragma unroll
    for (int ks = 0; ks < KSTEPS; ks++) {
        uint32_t ah[2][4], al[2][4];
#pragma unroll
        for (int mt = 0; mt < 2; mt++) {
            int r1 = rowg * 32 + mt * 16 + g;
            int r2 = r1 + 8;
            ah[mt][0] = lds_frag(smem + SM_A_HI, r1, 2 * ks, t);
            ah[mt][1] = lds_frag(smem + SM_A_HI, r2, 2 * ks, t);
            ah[mt][2] = lds_frag(smem + SM_A_HI, r1, 2 * ks + 1, t);
            ah[mt][3] = lds_frag(smem + SM_A_HI, r2, 2 * ks + 1, t);
            al[mt][0] = lds_frag(smem + SM_A_LO, r1, 2 * ks, t);
            al[mt][1] = lds_frag(smem + SM_A_LO, r2, 2 * ks, t);
            al[mt][2] = lds_frag(smem + SM_A_LO, r1, 2 * ks + 1, t);
            al[mt][3] = lds_frag(smem + SM_A_LO, r2, 2 * ks + 1, t);
        }
#pragma unroll
        for (int nt = 0; nt < 6; nt++) {
            int br = (nt >> 1) * 32 + colg * 16 + (nt & 1) * 8 + g;
            uint32_t bh[2], bl[2];
            bh[0] = lds_frag(smem + SM_B_HI, br, 2 * ks, t);
            bh[1] = lds_frag(smem + SM_B_HI, br, 2 * ks + 1, t);
            bl[0] = lds_frag(smem + SM_B_LO, br, 2 * ks, t);
            bl[1] = lds_frag(smem + SM_B_LO, br, 2 * ks + 1, t);
#pragma unroll
            for (int mt = 0; mt < 2; mt++) {
                mma16816(acc[mt][nt], ah[mt], bh);
                mma16816(acc[mt][nt], ah[mt], bl);
                mma16816(acc[mt][nt], al[mt], bh);
            }
        }
    }

    // epilogue
#pragma unroll
    for (int mt = 0; mt < 2; mt++) {
        int rbase = row0 + rowg * 32 + mt * 16 + g;
#pragma unroll
        for (int sub = 0; sub < 2; sub++) {
            int jj = j0 + colg * 16 + sub * 8 + t * 2;
            if (MODE == 0) {
#pragma unroll
                for (int g3 = 0; g3 < 3; g3++) {
                    int nt = 2 * g3 + sub;
                    __half2 v0 = __floats2half2_rn(acc[mt][nt][0], acc[mt][nt][1]);
                    __half2 v1 = __floats2half2_rn(acc[mt][nt][2], acc[mt][nt][3]);
                    *(__half2*)&gi[(size_t)rbase * H3 + g3 * 128 + jj] = v0;
                    *(__half2*)&gi[(size_t)(rbase + 8) * H3 + g3 * 128 + jj] = v1;
                }
            } else {
                float2 bihr = *(const float2*)&b_ih[jj];
                float2 bihz = *(const float2*)&b_ih[128 + jj];
                float2 bihn = *(const float2*)&b_ih[256 + jj];
                float2 bhhr = *(const float2*)&b_hh[jj];
                float2 bhhz = *(const float2*)&b_hh[128 + jj];
                float2 bhhn = *(const float2*)&b_hh[256 + jj];
#pragma unroll
                for (int q = 0; q < 2; q++) {
                    int rr = rbase + q * 8;
                    float2 gir = __half22float2(*(const __half2*)&gi[(size_t)rr * H3 + jj]);
                    float2 giz = __half22float2(*(const __half2*)&gi[(size_t)rr * H3 + 128 + jj]);
                    float2 gin = __half22float2(*(const __half2*)&gi[(size_t)rr * H3 + 256 + jj]);
                    float2 hp  = *(const float2*)&hprev[(size_t)rr * HH + jj];
                    float hn[2];
#pragma unroll
                    for (int c = 0; c < 2; c++) {
                        float ghr = acc[mt][sub][q * 2 + c];
                        float ghz = acc[mt][2 + sub][q * 2 + c];
                        float ghn = acc[mt][4 + sub][q * 2 + c];
                        float gir_c = (c == 0) ? gir.x : gir.y;
                        float giz_c = (c == 0) ? giz.x : giz.y;
                        float gin_c = (c == 0) ? gin.x : gin.y;
                        float bir = (c == 0) ? bihr.x : bihr.y;
                        float biz = (c == 0) ? bihz.x : bihz.y;
                        float bin = (c == 0) ? bihn.x : bihn.y;
                        float bhr = (c == 0) ? bhhr.x : bhhr.y;
                        float bhz = (c == 0) ? bhhz.x : bhhz.y;
                        float bhn = (c == 0) ? bhhn.x : bhhn.y;
                        float hpc = (c == 0) ? hp.x : hp.y;
                        float rv = sigmoidf_(gir_c + bir + ghr + bhr);
                        float zv = sigmoidf_(giz_c + biz + ghz + bhz);
                        float nv = tanhf(gin_c + bin + rv * (ghn + bhn));
                        hn[c] = (1.0f - zv) * nv + zv * hpc;
                    }
                    float2 ho; ho.x = hn[0]; ho.y = hn[1];
                    *(float2*)&hout[(size_t)rr * HH + jj] = ho;
                    __nv_bfloat16 hi0 = __float2bfloat16(hn[0]);
                    __nv_bfloat16 hi1 = __float2bfloat16(hn[1]);
                    __nv_bfloat162 hv, lv;
                    hv.x = hi0; hv.y = hi1;
                    lv.x = __float2bfloat16(hn[0] - __bfloat162float(hi0));
                    lv.y = __float2bfloat16(hn[1] - __bfloat162float(hi1));
                    *(__nv_bfloat162*)&houthi[(size_t)rr * HH + jj] = hv;
                    *(__nv_bfloat162*)&houtlo[(size_t)rr * HH + jj] = lv;
                }
            }
        }
    }
}

// ---------------- readout ----------------
__global__ void readout_kernel(const float* __restrict__ l1w, const float* __restrict__ l1b,
                               const float* __restrict__ l2w, const float* __restrict__ l2b,
                               const int* __restrict__ batch, const float* __restrict__ h,
                               float* __restrict__ out_mu, float* __restrict__ out_sigma) {
    int gt = blockIdx.x * blockDim.x + threadIdx.x;
    int n = gt >> 5;
    int lane = gt & 31;
    if (n >= NN) return;
    float s1 = 0.0f, s2 = 0.0f;
#pragma unroll
    for (int k = lane; k < HH; k += 32) {
        float v = fmaxf(h[(size_t)n * HH + k], 0.0f);
        s1 += v * l1w[k];
        s2 += v * l2w[k];
    }
#pragma unroll
    for (int o = 16; o; o >>= 1) {
        s1 += __shfl_down_sync(0xffffffffu, s1, o);
        s2 += __shfl_down_sync(0xffffffffu, s2, o);
    }
    if (lane == 0) {
        float mu = s1 + l1b[0];
        float sp = s2 + l2b[0];
        float sigma = fmaxf(sp, 0.0f) + log1pf(expf(-fabsf(sp)));
        out_mu[n] = mu;
        out_sigma[n] = sigma;
        atomicAdd(&g_mu_all[batch[n]], mu);
        atomicAdd(&g_sig_all[batch[n]], sigma);
    }
}

__global__ void correct_kernel(const int* __restrict__ batch,
                               const float* __restrict__ out_mu, const float* __restrict__ out_sigma,
                               float* __restrict__ out_mu_c) {
    int n = blockIdx.x * blockDim.x + threadIdx.x;
    if (n >= NN) return;
    int b = batch[n];
    out_mu_c[n] = out_mu[n] - g_mu_all[b] * (out_sigma[n] / g_sig_all[b]);
}

// ---------------- launch ----------------
extern "C" void kernel_launch(void* const* d_in, const int* in_sizes, int n_in,
                              void* d_out, int out_size) {
    const float* x      = (const float*)d_in[0];
    const int*   edge   = (const int*)d_in[1];
    const int*   batch  = (const int*)d_in[2];
    const float* lin0_w = (const float*)d_in[3];
    const float* ggc_w  = (const float*)d_in[4];
    const float* w_ih   = (const float*)d_in[5];
    const float* w_hh   = (const float*)d_in[6];
    const float* b_ih   = (const float*)d_in[7];
    const float* b_hh   = (const float*)d_in[8];
    const float* l1w    = (const float*)d_in[9];
    const float* l1b    = (const float*)d_in[10];
    const float* l2w    = (const float*)d_in[11];
    const float* l2b    = (const float*)d_in[12];

    float* out       = (float*)d_out;
    float* out_mu_c  = out;
    float* out_x1    = out + NN;
    float* out_sigma = out + NN + NN * EMB;
    float* out_mu    = out + NN + NN * EMB + NN;

    const int* src = edge;
    const int* dst = edge + EE;

    float *ph0, *ph1, *pcl;
    __half* pgi;
    __nv_bfloat16 *phhi0, *phlo0, *phhi1, *phlo1, *paghi, *paglo, *pclThi, *pclTlo, *pwhhhi, *pwhhlo;
    cudaGetSymbolAddress((void**)&ph0,    g_h0);
    cudaGetSymbolAddress((void**)&ph1,    g_h1);
    cudaGetSymbolAddress((void**)&pgi,    g_gi);
    cudaGetSymbolAddress((void**)&pcl,    g_cl);
    cudaGetSymbolAddress((void**)&phhi0,  g_hhi0);
    cudaGetSymbolAddress((void**)&phlo0,  g_hlo0);
    cudaGetSymbolAddress((void**)&phhi1,  g_hhi1);
    cudaGetSymbolAddress((void**)&phlo1,  g_hlo1);
    cudaGetSymbolAddress((void**)&paghi,  g_aghi);
    cudaGetSymbolAddress((void**)&paglo,  g_aglo);
    cudaGetSymbolAddress((void**)&pclThi, g_clT_hi);
    cudaGetSymbolAddress((void**)&pclTlo, g_clT_lo);
    cudaGetSymbolAddress((void**)&pwhhhi, g_whh_hi);
    cudaGetSymbolAddress((void**)&pwhhlo, g_whh_lo);

    cudaFuncSetAttribute((const void*)mma_tile_kernel<0, 8>, cudaFuncAttributeMaxDynamicSharedMemorySize, GSMEM);
    cudaFuncSetAttribute((const void*)mma_tile_kernel<1, 8>, cudaFuncAttributeMaxDynamicSharedMemorySize, GSMEM);
    cudaFuncSetAttribute((const void*)mma_tile_kernel<0, 4>, cudaFuncAttributeMaxDynamicSharedMemorySize, GSMEM);
    cudaFuncSetAttribute((const void*)mma_tile_kernel<1, 4>, cudaFuncAttributeMaxDynamicSharedMemorySize, GSMEM);

    zero_init_kernel<<<(NN + 255) / 256, 256>>>();
    count_deg_kernel<<<(EE + 255) / 256, 256>>>(dst);
    scan1_kernel<<<NBLK, SCAN_B>>>();
    scan2_kernel<<<1, 32>>>();
    scan3_kernel<<<(NN + 255) / 256, 256>>>();
    fill_csr_kernel<<<(EE + 255) / 256, 256>>>(src, dst);

    lin0_kernel<<<(NN + 3) / 4, 256>>>(x, lin0_w, out_x1);

    {
        dim3 gcl((H3 + 63) / 64, (HH + 63) / 64);
        for (int l = 0; l < LL; l++)
            gemm_kernel<true><<<gcl, 256>>>(ggc_w + l * HH * HH, w_ih, pcl + l * HH * H3, HH, H3, HH);
        conv_cl_kernel<<<(LL * H3 * HH + 255) / 256, 256>>>();
        conv_whh_kernel<<<(H3 * HH + 255) / 256, 256>>>(w_hh);
    }

    dim3 ggrid(4, NPAD / 128);
    for (int l = 0; l < LL; l++) {
        const float* hcur = (l & 1) ? ph1 : ph0;
        float* hnext      = (l & 1) ? ph0 : ph1;
        __nv_bfloat16* hhicur = (l & 1) ? phhi1 : phhi0;
        __nv_bfloat16* hlocur = (l & 1) ? phlo1 : phlo0;
        __nv_bfloat16* hhinxt = (l & 1) ? phhi0 : phhi1;
        __nv_bfloat16* hlonxt = (l & 1) ? phlo0 : phlo1;

        if (l == 0) {
            agg_kernel<true><<<(NN + 7) / 8, 256>>>(hcur);
            mma_tile_kernel<0, 4><<<ggrid, 256, GSMEM>>>(paghi, paglo,
                                                         pclThi + l * H3 * HH, pclTlo + l * H3 * HH,
                                                         pgi, nullptr, nullptr, nullptr,
                                                         nullptr, nullptr, nullptr);
            mma_tile_kernel<1, 4><<<ggrid, 256, GSMEM>>>(hhicur, hlocur, pwhhhi, pwhhlo,
                                                         pgi, b_ih, b_hh, hcur,
                                                         hnext, hhinxt, hlonxt);
        } else {
            agg_kernel<false><<<(NN + 7) / 8, 256>>>(hcur);
            mma_tile_kernel<0, 8><<<ggrid, 256, GSMEM>>>(paghi, paglo,
                                                         pclThi + l * H3 * HH, pclTlo + l * H3 * HH,
                                                         pgi, nullptr, nullptr, nullptr,
                                                         nullptr, nullptr, nullptr);
            mma_tile_kernel<1, 8><<<ggrid, 256, GSMEM>>>(hhicur, hlocur, pwhhhi, pwhhlo,
                                                         pgi, b_ih, b_hh, hcur,
                                                         hnext, hhinxt, hlonxt);
        }
    }

    readout_kernel<<<(NN * 32 + 255) / 256, 256>>>(l1w, l1b, l2w, l2b, batch, ph0, out_mu, out_sigma);
    correct_kernel<<<(NN + 255) / 256, 256>>>(batch, out_mu, out_sigma, out_mu_c);
}